// round 1
// baseline (speedup 1.0000x reference)
#include <cuda_runtime.h>
#include <cstdint>

#define GRID_W 32
#define NNODES 1024
#define BATCH 256
#define KDIM 256

// Scratch (device-global: no allocations allowed)
__device__ float g_buf1[BATCH * NNODES * 256];   // h1 (268MB) / later h3 (134MB)
__device__ float g_buf2[BATCH * NNODES * 256];   // h2 (268MB)
__device__ float g_part[16 * 2560];              // classifier partials

// ---------------------------------------------------------------------------
// Grid-graph helpers: adj = D^-1/2 (A + I) D^-1/2 with 5-point stencil.
// deg(i,j) = 1 + #neighbors in-bounds;  dis = deg^-0.5
// ---------------------------------------------------------------------------
__device__ __forceinline__ float disv(int i, int j) {
    int deg = 1 + (i > 0) + (i < GRID_W - 1) + (j > 0) + (j < GRID_W - 1);
    return deg == 5 ? 0.4472135954999579f
         : (deg == 4 ? 0.5f : 0.5773502691896258f);
}
__device__ __forceinline__ float rowsumv(int i, int j) {
    float d = disv(i, j);
    float s = d;
    if (i > 0)          s += disv(i - 1, j);
    if (i < GRID_W - 1) s += disv(i + 1, j);
    if (j > 0)          s += disv(i, j - 1);
    if (j < GRID_W - 1) s += disv(i, j + 1);
    return d * s;
}
__device__ __forceinline__ uint32_t f2tf(float x) {
    uint32_t r;
    asm("cvt.rna.tf32.f32 %0, %1;" : "=r"(r) : "f"(x));
    return r;
}

// ---------------------------------------------------------------------------
// Layer 1 fused: im2graph + stencil-aggregate (only 3 features) + 3->256
// linear + ReLU.   out[b][node][h] fp32.
// ---------------------------------------------------------------------------
__global__ void layer1_kernel(const float* __restrict__ x,
                              const float* __restrict__ W1,
                              const float* __restrict__ b1,
                              float* __restrict__ out) {
    const int gr = blockIdx.x;   // grid row 0..31
    const int b  = blockIdx.y;   // batch
    const int t  = threadIdx.x;  // 256 threads = output feature
    __shared__ float aggs[32][3];

    if (t < 96) {
        int f = t / 32, gc = t % 32;
        const float* xp = x + ((size_t)(b * 3 + f)) * NNODES;  // x[b][f][.][.]
        float dm = disv(gr, gc);
        float a = dm * xp[gr * 32 + gc];
        if (gr > 0)  a = fmaf(disv(gr - 1, gc), xp[(gr - 1) * 32 + gc], a);
        if (gr < 31) a = fmaf(disv(gr + 1, gc), xp[(gr + 1) * 32 + gc], a);
        if (gc > 0)  a = fmaf(disv(gr, gc - 1), xp[gr * 32 + gc - 1], a);
        if (gc < 31) a = fmaf(disv(gr, gc + 1), xp[gr * 32 + gc + 1], a);
        aggs[gc][f] = dm * a;
    }
    __syncthreads();

    float w0 = W1[t * 3 + 0], w1 = W1[t * 3 + 1], w2 = W1[t * 3 + 2];
    float bb = b1[t];
    float* op = out + ((size_t)b * NNODES + gr * 32) * 256 + t;
    #pragma unroll 4
    for (int gc = 0; gc < 32; ++gc) {
        float rs = rowsumv(gr, gc);
        float v = fmaf(aggs[gc][0], w0,
                  fmaf(aggs[gc][1], w1,
                  fmaf(aggs[gc][2], w2, rs * bb)));
        op[(size_t)gc * 256] = fmaxf(v, 0.0f);
    }
}

// ---------------------------------------------------------------------------
// Fused stencil-aggregate + GEMM + bias + ReLU  (layers 2 and 3).
//   out[b][m][h] = relu( sum_f agg(in)[b][m][f] * W[h][f] + rowsum[m]*bias[h] )
// CTA tile: M=128 nodes (4 grid rows of one batch) x N=128 out-features,
// K chunks of 32.  8 warps, warp tile 64x32, mma.sync m16n8k8 tf32.
// A-tile producer applies the 5-tap stencil straight from gmem (halo in L2).
// ---------------------------------------------------------------------------
__global__ __launch_bounds__(256, 2)
void gcn_gemm_kernel(const float* __restrict__ in,
                     const float* __restrict__ W,
                     const float* __restrict__ bias,
                     float* __restrict__ out, int HOUT) {
    const int j  = blockIdx.x;    // 128-wide output-feature block
    const int rb = blockIdx.y;    // node-row block (4 grid rows)
    const int b  = blockIdx.z;    // batch
    const int t    = threadIdx.x;
    const int warp = t >> 5, lane = t & 31;
    const int g4 = lane >> 2, l4 = lane & 3;
    const int warpM = (warp >> 2) * 64;   // 2 warps along M
    const int warpN = (warp & 3) * 32;    // 4 warps along N

    __shared__ float As[128][36];   // pitch 36 floats: conflict-free frags,
    __shared__ float Bs[128][36];   // rows stay 16B aligned (144B pitch)

    float acc[4][4][4] = {};        // [mi][ni][c]

    const int r0 = rb * 4;
    const float* inb = in + (size_t)b * NNODES * KDIM;
    const float* Wj  = W + (size_t)j * 128 * KDIM;

    for (int k0 = 0; k0 < KDIM; k0 += 32) {
        __syncthreads();
        // ---- A tile: stencil-aggregated input, rounded to tf32 ----
        #pragma unroll
        for (int it = 0; it < 4; ++it) {
            int id = t + it * 256;            // 1024 float4 slots
            int m = id >> 3, kq = id & 7;
            int gr = r0 + (m >> 5), gc = m & 31;
            int node = gr * GRID_W + gc;
            const float* bp = inb + (size_t)node * KDIM + k0 + kq * 4;
            float dm = disv(gr, gc);
            float4 v = *(const float4*)bp;
            float sx = dm * v.x, sy = dm * v.y, sz = dm * v.z, sw = dm * v.w;
            if (gr > 0) {
                float w0 = disv(gr - 1, gc);
                float4 u = *(const float4*)(bp - GRID_W * KDIM);
                sx = fmaf(w0, u.x, sx); sy = fmaf(w0, u.y, sy);
                sz = fmaf(w0, u.z, sz); sw = fmaf(w0, u.w, sw);
            }
            if (gr < GRID_W - 1) {
                float w0 = disv(gr + 1, gc);
                float4 u = *(const float4*)(bp + GRID_W * KDIM);
                sx = fmaf(w0, u.x, sx); sy = fmaf(w0, u.y, sy);
                sz = fmaf(w0, u.z, sz); sw = fmaf(w0, u.w, sw);
            }
            if (gc > 0) {
                float w0 = disv(gr, gc - 1);
                float4 u = *(const float4*)(bp - KDIM);
                sx = fmaf(w0, u.x, sx); sy = fmaf(w0, u.y, sy);
                sz = fmaf(w0, u.z, sz); sw = fmaf(w0, u.w, sw);
            }
            if (gc < GRID_W - 1) {
                float w0 = disv(gr, gc + 1);
                float4 u = *(const float4*)(bp + KDIM);
                sx = fmaf(w0, u.x, sx); sy = fmaf(w0, u.y, sy);
                sz = fmaf(w0, u.z, sz); sw = fmaf(w0, u.w, sw);
            }
            uint4 o;
            o.x = f2tf(dm * sx); o.y = f2tf(dm * sy);
            o.z = f2tf(dm * sz); o.w = f2tf(dm * sw);
            *(uint4*)(&As[m][kq * 4]) = o;
        }
        // ---- B tile: weights, rounded to tf32 ----
        #pragma unroll
        for (int it = 0; it < 4; ++it) {
            int id = t + it * 256;
            int n = id >> 3, kq = id & 7;
            float4 v = *(const float4*)(Wj + (size_t)n * KDIM + k0 + kq * 4);
            uint4 o;
            o.x = f2tf(v.x); o.y = f2tf(v.y); o.z = f2tf(v.z); o.w = f2tf(v.w);
            *(uint4*)(&Bs[n][kq * 4]) = o;
        }
        __syncthreads();

        // ---- mma over the 32-wide K chunk ----
        #pragma unroll
        for (int kk = 0; kk < 32; kk += 8) {
            uint32_t af[4][4], bf[4][2];
            #pragma unroll
            for (int mi = 0; mi < 4; mi++) {
                int m = warpM + mi * 16;
                af[mi][0] = __float_as_uint(As[m + g4    ][kk + l4    ]);
                af[mi][1] = __float_as_uint(As[m + g4 + 8][kk + l4    ]);
                af[mi][2] = __float_as_uint(As[m + g4    ][kk + l4 + 4]);
                af[mi][3] = __float_as_uint(As[m + g4 + 8][kk + l4 + 4]);
            }
            #pragma unroll
            for (int ni = 0; ni < 4; ni++) {
                int n = warpN + ni * 8;
                bf[ni][0] = __float_as_uint(Bs[n + g4][kk + l4    ]);
                bf[ni][1] = __float_as_uint(Bs[n + g4][kk + l4 + 4]);
            }
            #pragma unroll
            for (int mi = 0; mi < 4; mi++)
                #pragma unroll
                for (int ni = 0; ni < 4; ni++)
                    asm volatile(
                        "mma.sync.aligned.m16n8k8.row.col.f32.tf32.tf32.f32 "
                        "{%0,%1,%2,%3},{%4,%5,%6,%7},{%8,%9},{%0,%1,%2,%3};\n"
                        : "+f"(acc[mi][ni][0]), "+f"(acc[mi][ni][1]),
                          "+f"(acc[mi][ni][2]), "+f"(acc[mi][ni][3])
                        : "r"(af[mi][0]), "r"(af[mi][1]),
                          "r"(af[mi][2]), "r"(af[mi][3]),
                          "r"(bf[ni][0]), "r"(bf[ni][1]));
        }
    }

    // ---- epilogue: + rowsum*bias, ReLU, store ----
    #pragma unroll
    for (int mi = 0; mi < 4; mi++) {
        #pragma unroll
        for (int r = 0; r < 2; r++) {
            int m = warpM + mi * 16 + g4 + 8 * r;
            int gr = r0 + (m >> 5), gc = m & 31;
            int node = gr * GRID_W + gc;
            float rs = rowsumv(gr, gc);
            float* op = out + ((size_t)b * NNODES + node) * HOUT;
            #pragma unroll
            for (int ni = 0; ni < 4; ni++) {
                int n = j * 128 + warpN + ni * 8 + 2 * l4;
                float2 v;
                v.x = fmaxf(fmaf(rs, bias[n    ], acc[mi][ni][2 * r    ]), 0.0f);
                v.y = fmaxf(fmaf(rs, bias[n + 1], acc[mi][ni][2 * r + 1]), 0.0f);
                *(float2*)(op + n) = v;
            }
        }
    }
}

// ---------------------------------------------------------------------------
// Classifier stage 1: out[b][c] = sum_i h3[b][i] * Wc[c][i]
// K=131072 split into 16 chunks; 8 batches x 10 classes per CTA so each Wc
// element loaded once serves 8 batches (Wc stays resident in L2).
// ---------------------------------------------------------------------------
__global__ void cls_partial_kernel(const float* __restrict__ h,
                                   const float* __restrict__ Wc,
                                   float* __restrict__ part) {
    const int ks = blockIdx.x;   // 0..15  K-split
    const int bg = blockIdx.y;   // 0..31  batch group of 8
    const int t  = threadIdx.x;  // 256
    float acc[10][8] = {};
    const int base = ks * 8192;
    const float* hb = h + (size_t)(bg * 8) * 131072;

    for (int it = 0; it < 32; ++it) {
        int idx = base + it * 256 + t;
        float wv[10];
        #pragma unroll
        for (int c = 0; c < 10; c++) wv[c] = Wc[(size_t)c * 131072 + idx];
        #pragma unroll
        for (int g = 0; g < 8; g++) {
            float hv = hb[(size_t)g * 131072 + idx];
            #pragma unroll
            for (int c = 0; c < 10; c++) acc[c][g] = fmaf(hv, wv[c], acc[c][g]);
        }
    }
    // warp reduce all 80 accumulators
    #pragma unroll
    for (int c = 0; c < 10; c++)
        #pragma unroll
        for (int g = 0; g < 8; g++) {
            float v = acc[c][g];
            for (int o = 16; o; o >>= 1) v += __shfl_down_sync(0xffffffffu, v, o);
            acc[c][g] = v;
        }
    __shared__ float red[8][80];
    if ((t & 31) == 0) {
        int w = t >> 5;
        #pragma unroll
        for (int c = 0; c < 10; c++)
            #pragma unroll
            for (int g = 0; g < 8; g++) red[w][c * 8 + g] = acc[c][g];
    }
    __syncthreads();
    if (t < 80) {
        float s = 0.f;
        #pragma unroll
        for (int w = 0; w < 8; w++) s += red[w][t];
        part[ks * 2560 + bg * 80 + t] = s;
    }
}

__global__ void cls_final_kernel(const float* __restrict__ part,
                                 const float* __restrict__ bc,
                                 float* __restrict__ out) {
    int i = blockIdx.x * 256 + threadIdx.x;
    if (i >= 2560) return;
    int b = i / 10, c = i % 10;
    int bg = b >> 3, g = b & 7;
    float s = bc[c];
    #pragma unroll
    for (int ks = 0; ks < 16; ks++)
        s += part[ks * 2560 + bg * 80 + c * 8 + g];
    out[i] = s;
}

// ---------------------------------------------------------------------------
extern "C" void kernel_launch(void* const* d_in, const int* in_sizes, int n_in,
                              void* d_out, int out_size) {
    const float* x  = (const float*)d_in[0];
    const float* W1 = (const float*)d_in[1];
    const float* b1 = (const float*)d_in[2];
    const float* W2 = (const float*)d_in[3];
    const float* b2 = (const float*)d_in[4];
    const float* W3 = (const float*)d_in[5];
    const float* b3 = (const float*)d_in[6];
    const float* Wc = (const float*)d_in[7];
    const float* bc = (const float*)d_in[8];
    float* out = (float*)d_out;

    float *buf1, *buf2, *part;
    cudaGetSymbolAddress((void**)&buf1, g_buf1);
    cudaGetSymbolAddress((void**)&buf2, g_buf2);
    cudaGetSymbolAddress((void**)&part, g_part);

    // layer1: x -> h1 (buf1)
    layer1_kernel<<<dim3(GRID_W, BATCH), 256>>>(x, W1, b1, buf1);
    // layer2: agg(h1) @ W2^T -> h2 (buf2), HOUT=256
    gcn_gemm_kernel<<<dim3(2, 8, BATCH), 256>>>(buf1, W2, b2, buf2, 256);
    // layer3: agg(h2) @ W3^T -> h3 (buf1), HOUT=128
    gcn_gemm_kernel<<<dim3(1, 8, BATCH), 256>>>(buf2, W3, b3, buf1, 128);
    // classifier
    cls_partial_kernel<<<dim3(16, 32), 256>>>(buf1, Wc, part);
    cls_final_kernel<<<10, 256>>>(part, bc, out);
}

// round 2
// speedup vs baseline: 1.8005x; 1.8005x over previous
#include <cuda_runtime.h>
#include <cuda_fp16.h>
#include <cstdint>

#define GRID_W 32
#define NNODES 1024
#define BATCH 256
#define KDIM 256

// Scratch (device globals: no allocations allowed)
__device__ __half g_h1[BATCH * NNODES * 256];          // 134MB: h1, later h3
__device__ __half g_h2[BATCH * NNODES * 256];          // 134MB: h2
__device__ __half g_w[65536 + 32768 + 1310720];        // fp16 W2|W3|Wc
__device__ float  g_part[16 * 2560];

// ---------------------------------------------------------------------------
// Grid-graph stencil weights: adj = D^-1/2 (A+I) D^-1/2, deg in {3,4,5}
// ---------------------------------------------------------------------------
__device__ __forceinline__ float disv(int i, int j) {
    int deg = 1 + (i > 0) + (i < GRID_W - 1) + (j > 0) + (j < GRID_W - 1);
    return deg == 5 ? 0.4472135954999579f
         : (deg == 4 ? 0.5f : 0.5773502691896258f);
}
__device__ __forceinline__ float rowsumv(int i, int j) {
    float d = disv(i, j);
    float s = d;
    if (i > 0)          s += disv(i - 1, j);
    if (i < GRID_W - 1) s += disv(i + 1, j);
    if (j > 0)          s += disv(i, j - 1);
    if (j < GRID_W - 1) s += disv(i, j + 1);
    return d * s;
}

__device__ __forceinline__ void h8fma(float s[8], uint4 u, float w) {
    __half2 h0 = *(__half2*)&u.x, h1 = *(__half2*)&u.y;
    __half2 h2 = *(__half2*)&u.z, h3 = *(__half2*)&u.w;
    float2 f;
    f = __half22float2(h0); s[0] = fmaf(w, f.x, s[0]); s[1] = fmaf(w, f.y, s[1]);
    f = __half22float2(h1); s[2] = fmaf(w, f.x, s[2]); s[3] = fmaf(w, f.y, s[3]);
    f = __half22float2(h2); s[4] = fmaf(w, f.x, s[4]); s[5] = fmaf(w, f.y, s[5]);
    f = __half22float2(h3); s[6] = fmaf(w, f.x, s[6]); s[7] = fmaf(w, f.y, s[7]);
}

// ---------------------------------------------------------------------------
// Pre-convert weights fp32 -> fp16 (W2 | W3 | Wc packed in g_w)
// ---------------------------------------------------------------------------
__global__ void convert_w_kernel(const float* __restrict__ W2,
                                 const float* __restrict__ W3,
                                 const float* __restrict__ Wc,
                                 __half* __restrict__ o) {
    int i = blockIdx.x * 256 + threadIdx.x;
    if (i < 65536)   o[i] = __float2half(W2[i]);
    if (i < 32768)   o[65536 + i] = __float2half(W3[i]);
    if (i < 1310720) o[98304 + i] = __float2half(Wc[i]);
}

// ---------------------------------------------------------------------------
// Layer 1 fused: im2graph + stencil + 3->256 linear + ReLU -> fp16
// ---------------------------------------------------------------------------
__global__ void layer1_kernel(const float* __restrict__ x,
                              const float* __restrict__ W1,
                              const float* __restrict__ b1,
                              __half* __restrict__ out) {
    const int gr = blockIdx.x;   // grid row
    const int b  = blockIdx.y;   // batch
    const int t  = threadIdx.x;  // 256 = output feature
    __shared__ float aggs[32][3];

    if (t < 96) {
        int f = t / 32, gc = t % 32;
        const float* xp = x + ((size_t)(b * 3 + f)) * NNODES;
        float dm = disv(gr, gc);
        float a = dm * xp[gr * 32 + gc];
        if (gr > 0)  a = fmaf(disv(gr - 1, gc), xp[(gr - 1) * 32 + gc], a);
        if (gr < 31) a = fmaf(disv(gr + 1, gc), xp[(gr + 1) * 32 + gc], a);
        if (gc > 0)  a = fmaf(disv(gr, gc - 1), xp[gr * 32 + gc - 1], a);
        if (gc < 31) a = fmaf(disv(gr, gc + 1), xp[gr * 32 + gc + 1], a);
        aggs[gc][f] = dm * a;
    }
    __syncthreads();

    float w0 = W1[t * 3 + 0], w1 = W1[t * 3 + 1], w2 = W1[t * 3 + 2];
    float bb = b1[t];
    __half* op = out + ((size_t)b * NNODES + gr * 32) * 256 + t;
    #pragma unroll 4
    for (int gc = 0; gc < 32; ++gc) {
        float rs = rowsumv(gr, gc);
        float v = fmaf(aggs[gc][0], w0,
                  fmaf(aggs[gc][1], w1,
                  fmaf(aggs[gc][2], w2, rs * bb)));
        op[(size_t)gc * 256] = __float2half(fmaxf(v, 0.0f));
    }
}

// ---------------------------------------------------------------------------
// Fused stencil-aggregate + GEMM(fp16 mma) + bias + ReLU. Layers 2 and 3.
// CTA: M=128 nodes x N=NT out-features, K chunks of 32. 512 threads,
// 16 warps. NT=256: 2x8 warps of 64x32. NT=128: 4x4 warps of 32x32.
// Software pipeline: center-A + B prefetched one chunk ahead.
// ---------------------------------------------------------------------------
template<int NT>
__global__ __launch_bounds__(512, 1)
void gcn_gemm_f16(const __half* __restrict__ in,
                  const __half* __restrict__ W,
                  const float* __restrict__ bias,
                  __half* __restrict__ out) {
    const int rb = blockIdx.x;   // node-row block (4 grid rows)
    const int b  = blockIdx.y;   // batch
    const int t    = threadIdx.x;
    const int warp = t >> 5, lane = t & 31;
    const int g4 = lane >> 2, l4 = lane & 3;
    constexpr int WM = (NT == 256) ? 64 : 32;
    constexpr int MI = WM / 16;
    constexpr int NB = NT * 32 / 8 / 512;   // B uint4 slots per thread
    const int warpM = (NT == 256) ? (warp >> 3) * 64 : (warp >> 2) * 32;
    const int warpN = (NT == 256) ? (warp & 7) * 32 : (warp & 3) * 32;

    __shared__ __half As[128][40];   // pitch 40 halfs: conflict-free frag LDS
    __shared__ __half Bs[NT][40];

    float acc[MI][4][4] = {};

    const int r0 = rb * 4;
    const __half* inb = in + (size_t)b * NNODES * KDIM;

    // A-fill coordinates: thread t handles row am, uint4 slot aq (8 halfs)
    const int am = t >> 2, aq = t & 3;
    const int agr = r0 + (am >> 5), agc = am & 31;
    const __half* abp = inb + (size_t)(agr * GRID_W + agc) * KDIM + aq * 8;
    const float dC = disv(agr, agc);
    const float dU = (agr > 0)          ? disv(agr - 1, agc) : 0.f;
    const float dD = (agr < GRID_W - 1) ? disv(agr + 1, agc) : 0.f;
    const float dL = (agc > 0)          ? disv(agr, agc - 1) : 0.f;
    const float dR = (agc < GRID_W - 1) ? disv(agr, agc + 1) : 0.f;

    // B-fill coordinates
    int bn[NB], bq[NB];
    #pragma unroll
    for (int s = 0; s < NB; ++s) {
        int id = t + s * 512;
        bn[s] = id >> 2; bq[s] = id & 3;
    }

    // prefetch chunk 0: center A + B
    uint4 aC = *(const uint4*)abp;
    uint4 bReg[NB];
    #pragma unroll
    for (int s = 0; s < NB; ++s)
        bReg[s] = *(const uint4*)(W + (size_t)bn[s] * KDIM + bq[s] * 8);

    const uint4 Z = make_uint4(0, 0, 0, 0);

    for (int k0 = 0; k0 < KDIM; k0 += 32) {
        // neighbor taps for this chunk (gmem; overlap barrier-arrival skew)
        uint4 uU = dU != 0.f ? *(const uint4*)(abp - GRID_W * KDIM) : Z;
        uint4 uD = dD != 0.f ? *(const uint4*)(abp + GRID_W * KDIM) : Z;
        uint4 uL = dL != 0.f ? *(const uint4*)(abp - KDIM) : Z;
        uint4 uR = dR != 0.f ? *(const uint4*)(abp + KDIM) : Z;

        __syncthreads();   // previous mma done reading smem

        // stencil -> As (fp16)
        float s[8] = {};
        h8fma(s, aC, dC);
        if (dU != 0.f) h8fma(s, uU, dU);
        if (dD != 0.f) h8fma(s, uD, dD);
        if (dL != 0.f) h8fma(s, uL, dL);
        if (dR != 0.f) h8fma(s, uR, dR);
        uint4 o;
        *(__half2*)&o.x = __floats2half2_rn(dC * s[0], dC * s[1]);
        *(__half2*)&o.y = __floats2half2_rn(dC * s[2], dC * s[3]);
        *(__half2*)&o.z = __floats2half2_rn(dC * s[4], dC * s[5]);
        *(__half2*)&o.w = __floats2half2_rn(dC * s[6], dC * s[7]);
        *(uint4*)&As[am][aq * 8] = o;
        #pragma unroll
        for (int si = 0; si < NB; ++si)
            *(uint4*)&Bs[bn[si]][bq[si] * 8] = bReg[si];

        __syncthreads();

        abp += 32;
        if (k0 + 32 < KDIM) {   // prefetch next chunk (overlaps mma below)
            aC = *(const uint4*)abp;
            #pragma unroll
            for (int si = 0; si < NB; ++si)
                bReg[si] = *(const uint4*)(W + (size_t)bn[si] * KDIM +
                                           (k0 + 32) + bq[si] * 8);
        }

        // mma over 32-wide K chunk: 2 steps of k16
        #pragma unroll
        for (int kk = 0; kk < 32; kk += 16) {
            uint32_t af[MI][4], bf[4][2];
            #pragma unroll
            for (int mi = 0; mi < MI; mi++) {
                int m = warpM + mi * 16;
                af[mi][0] = *(uint32_t*)&As[m + g4    ][kk + l4 * 2    ];
                af[mi][1] = *(uint32_t*)&As[m + g4 + 8][kk + l4 * 2    ];
                af[mi][2] = *(uint32_t*)&As[m + g4    ][kk + l4 * 2 + 8];
                af[mi][3] = *(uint32_t*)&As[m + g4 + 8][kk + l4 * 2 + 8];
            }
            #pragma unroll
            for (int ni = 0; ni < 4; ni++) {
                int n = warpN + ni * 8;
                bf[ni][0] = *(uint32_t*)&Bs[n + g4][kk + l4 * 2    ];
                bf[ni][1] = *(uint32_t*)&Bs[n + g4][kk + l4 * 2 + 8];
            }
            #pragma unroll
            for (int mi = 0; mi < MI; mi++)
                #pragma unroll
                for (int ni = 0; ni < 4; ni++)
                    asm volatile(
                        "mma.sync.aligned.m16n8k16.row.col.f32.f16.f16.f32 "
                        "{%0,%1,%2,%3},{%4,%5,%6,%7},{%8,%9},{%0,%1,%2,%3};\n"
                        : "+f"(acc[mi][ni][0]), "+f"(acc[mi][ni][1]),
                          "+f"(acc[mi][ni][2]), "+f"(acc[mi][ni][3])
                        : "r"(af[mi][0]), "r"(af[mi][1]),
                          "r"(af[mi][2]), "r"(af[mi][3]),
                          "r"(bf[ni][0]), "r"(bf[ni][1]));
        }
    }

    // epilogue: + rowsum*bias, ReLU, fp16 store
    #pragma unroll
    for (int mi = 0; mi < MI; mi++) {
        #pragma unroll
        for (int r = 0; r < 2; r++) {
            int m = warpM + mi * 16 + g4 + 8 * r;
            int gr = r0 + (m >> 5), gc = m & 31;
            float rs = rowsumv(gr, gc);
            __half* op = out + ((size_t)b * NNODES + gr * GRID_W + gc) * NT;
            #pragma unroll
            for (int ni = 0; ni < 4; ni++) {
                int n = warpN + ni * 8 + 2 * l4;
                float vx = fmaxf(fmaf(rs, bias[n    ], acc[mi][ni][2 * r    ]), 0.f);
                float vy = fmaxf(fmaf(rs, bias[n + 1], acc[mi][ni][2 * r + 1]), 0.f);
                *(__half2*)(op + n) = __floats2half2_rn(vx, vy);
            }
        }
    }
}

// ---------------------------------------------------------------------------
// Classifier: out[b][c] = sum_i h3[b][i] * Wc[c][i], fp16 inputs.
// K=65536 half2 split 16 ways; 8 batches x 10 classes per CTA.
// ---------------------------------------------------------------------------
__global__ void cls_partial_kernel(const __half2* __restrict__ h,
                                   const __half2* __restrict__ Wc,
                                   float* __restrict__ part) {
    const int ks = blockIdx.x;   // 0..15
    const int bg = blockIdx.y;   // 0..31
    const int t  = threadIdx.x;  // 256
    float acc[10][8] = {};
    const int base = ks * 4096;
    const __half2* hb = h + (size_t)(bg * 8) * 65536;

    for (int it = 0; it < 16; ++it) {
        int idx = base + it * 256 + t;
        float2 wf[10];
        #pragma unroll
        for (int c = 0; c < 10; c++)
            wf[c] = __half22float2(Wc[(size_t)c * 65536 + idx]);
        #pragma unroll
        for (int g = 0; g < 8; g++) {
            float2 hv = __half22float2(hb[(size_t)g * 65536 + idx]);
            #pragma unroll
            for (int c = 0; c < 10; c++)
                acc[c][g] = fmaf(hv.x, wf[c].x, fmaf(hv.y, wf[c].y, acc[c][g]));
        }
    }
    #pragma unroll
    for (int c = 0; c < 10; c++)
        #pragma unroll
        for (int g = 0; g < 8; g++) {
            float v = acc[c][g];
            for (int o = 16; o; o >>= 1) v += __shfl_down_sync(0xffffffffu, v, o);
            acc[c][g] = v;
        }
    __shared__ float red[8][80];
    if ((t & 31) == 0) {
        int w = t >> 5;
        #pragma unroll
        for (int c = 0; c < 10; c++)
            #pragma unroll
            for (int g = 0; g < 8; g++) red[w][c * 8 + g] = acc[c][g];
    }
    __syncthreads();
    if (t < 80) {
        float s = 0.f;
        #pragma unroll
        for (int w = 0; w < 8; w++) s += red[w][t];
        part[ks * 2560 + bg * 80 + t] = s;
    }
}

__global__ void cls_final_kernel(const float* __restrict__ part,
                                 const float* __restrict__ bc,
                                 float* __restrict__ out) {
    int i = blockIdx.x * 256 + threadIdx.x;
    if (i >= 2560) return;
    int b = i / 10, c = i % 10;
    int bg = b >> 3, g = b & 7;
    float s = bc[c];
    #pragma unroll
    for (int ks = 0; ks < 16; ks++)
        s += part[ks * 2560 + bg * 80 + c * 8 + g];
    out[i] = s;
}

// ---------------------------------------------------------------------------
extern "C" void kernel_launch(void* const* d_in, const int* in_sizes, int n_in,
                              void* d_out, int out_size) {
    const float* x  = (const float*)d_in[0];
    const float* W1 = (const float*)d_in[1];
    const float* b1 = (const float*)d_in[2];
    const float* W2 = (const float*)d_in[3];
    const float* b2 = (const float*)d_in[4];
    const float* W3 = (const float*)d_in[5];
    const float* b3 = (const float*)d_in[6];
    const float* Wc = (const float*)d_in[7];
    const float* bc = (const float*)d_in[8];
    float* out = (float*)d_out;

    __half *h1, *h2, *w;
    float *part;
    cudaGetSymbolAddress((void**)&h1, g_h1);
    cudaGetSymbolAddress((void**)&h2, g_h2);
    cudaGetSymbolAddress((void**)&w,  g_w);
    cudaGetSymbolAddress((void**)&part, g_part);

    convert_w_kernel<<<5120, 256>>>(W2, W3, Wc, w);
    layer1_kernel<<<dim3(GRID_W, BATCH), 256>>>(x, W1, b1, h1);
    gcn_gemm_f16<256><<<dim3(8, BATCH), 512>>>(h1, w, b2, h2);
    gcn_gemm_f16<128><<<dim3(8, BATCH), 512>>>(h2, w + 65536, b3, h1);
    cls_partial_kernel<<<dim3(16, 32), 256>>>((const __half2*)h1,
                                              (const __half2*)(w + 98304), part);
    cls_final_kernel<<<10, 256>>>(part, bc, out);
}

// round 3
// speedup vs baseline: 1.8785x; 1.0433x over previous
#include <cuda_runtime.h>
#include <cuda_fp16.h>
#include <cstdint>

#define GRID_W 32
#define NNODES 1024
#define BATCH 256
#define KDIM 256

// Scratch (device globals: no allocations allowed)
__device__ __half g_h1[BATCH * NNODES * 256];          // 134MB: h1, later h3
__device__ __half g_h2[BATCH * NNODES * 256];          // 134MB: h2
__device__ __half g_w[65536 + 32768 + 1310720];        // fp16 W2|W3|Wc
__device__ float  g_part[16 * 2560];

// ---------------------------------------------------------------------------
// Stencil weights: adj = D^-1/2 (A+I) D^-1/2, deg in {3,4,5}
// ---------------------------------------------------------------------------
__device__ __forceinline__ float disv(int i, int j) {
    int deg = 1 + (i > 0) + (i < GRID_W - 1) + (j > 0) + (j < GRID_W - 1);
    return deg == 5 ? 0.4472135954999579f
         : (deg == 4 ? 0.5f : 0.5773502691896258f);
}
__device__ __forceinline__ float rowsumv(int i, int j) {
    float d = disv(i, j);
    float s = d;
    if (i > 0)          s += disv(i - 1, j);
    if (i < GRID_W - 1) s += disv(i + 1, j);
    if (j > 0)          s += disv(i, j - 1);
    if (j < GRID_W - 1) s += disv(i, j + 1);
    return d * s;
}
__device__ __forceinline__ void h8fma(float s[8], uint4 u, float w) {
    __half2 h0 = *(__half2*)&u.x, h1 = *(__half2*)&u.y;
    __half2 h2 = *(__half2*)&u.z, h3 = *(__half2*)&u.w;
    float2 f;
    f = __half22float2(h0); s[0] = fmaf(w, f.x, s[0]); s[1] = fmaf(w, f.y, s[1]);
    f = __half22float2(h1); s[2] = fmaf(w, f.x, s[2]); s[3] = fmaf(w, f.y, s[3]);
    f = __half22float2(h2); s[4] = fmaf(w, f.x, s[4]); s[5] = fmaf(w, f.y, s[5]);
    f = __half22float2(h3); s[6] = fmaf(w, f.x, s[6]); s[7] = fmaf(w, f.y, s[7]);
}
__device__ __forceinline__ void ldsm4(uint32_t r[4], uint32_t addr) {
    asm volatile("ldmatrix.sync.aligned.m8n8.x4.shared.b16 {%0,%1,%2,%3}, [%4];"
                 : "=r"(r[0]), "=r"(r[1]), "=r"(r[2]), "=r"(r[3]) : "r"(addr));
}
__device__ __forceinline__ void cpa16(uint32_t dst, const void* src) {
    asm volatile("cp.async.ca.shared.global [%0], [%1], 16;" :: "r"(dst), "l"(src));
}

// ---------------------------------------------------------------------------
// Pre-convert weights fp32 -> fp16 (W2 | W3 | Wc packed)
// ---------------------------------------------------------------------------
__global__ void convert_w_kernel(const float* __restrict__ W2,
                                 const float* __restrict__ W3,
                                 const float* __restrict__ Wc,
                                 __half* __restrict__ o) {
    int i = blockIdx.x * 256 + threadIdx.x;
    if (i < 65536)   o[i] = __float2half(W2[i]);
    if (i < 32768)   o[65536 + i] = __float2half(W3[i]);
    if (i < 1310720) o[98304 + i] = __float2half(Wc[i]);
}

// ---------------------------------------------------------------------------
// Layer 1 fused: im2graph + stencil + 3->256 linear + ReLU -> fp16
// ---------------------------------------------------------------------------
__global__ void layer1_kernel(const float* __restrict__ x,
                              const float* __restrict__ W1,
                              const float* __restrict__ b1,
                              __half* __restrict__ out) {
    const int gr = blockIdx.x, b = blockIdx.y, t = threadIdx.x;
    __shared__ float aggs[32][3];
    if (t < 96) {
        int f = t / 32, gc = t % 32;
        const float* xp = x + ((size_t)(b * 3 + f)) * NNODES;
        float dm = disv(gr, gc);
        float a = dm * xp[gr * 32 + gc];
        if (gr > 0)  a = fmaf(disv(gr - 1, gc), xp[(gr - 1) * 32 + gc], a);
        if (gr < 31) a = fmaf(disv(gr + 1, gc), xp[(gr + 1) * 32 + gc], a);
        if (gc > 0)  a = fmaf(disv(gr, gc - 1), xp[gr * 32 + gc - 1], a);
        if (gc < 31) a = fmaf(disv(gr, gc + 1), xp[gr * 32 + gc + 1], a);
        aggs[gc][f] = dm * a;
    }
    __syncthreads();
    float w0 = W1[t * 3 + 0], w1 = W1[t * 3 + 1], w2 = W1[t * 3 + 2];
    float bb = b1[t];
    __half* op = out + ((size_t)b * NNODES + gr * 32) * 256 + t;
    #pragma unroll 4
    for (int gc = 0; gc < 32; ++gc) {
        float rs = rowsumv(gr, gc);
        float v = fmaf(aggs[gc][0], w0,
                  fmaf(aggs[gc][1], w1,
                  fmaf(aggs[gc][2], w2, rs * bb)));
        op[(size_t)gc * 256] = __float2half(fmaxf(v, 0.0f));
    }
}

// ---------------------------------------------------------------------------
// Fused stencil + GEMM (fp16 mma, ldmatrix, cp.async, double-buffered smem)
// CTA: 256 thr, tile M=64 nodes (2 grid rows) x N=128, K chunks of 32.
// 8 warps at 32x32. grid = (16 m-blocks, HOUT/128, batch)
// ---------------------------------------------------------------------------
#define AS_ST 5120      // bytes per A stage (64*40*2)
#define BS_ST 10240     // bytes per B stage (128*40*2)

__global__ __launch_bounds__(256, 3)
void gcn_gemm_v3(const __half* __restrict__ in,
                 const __half* __restrict__ W,
                 const float* __restrict__ bias,
                 __half* __restrict__ out, int HOUT) {
    const int mb = blockIdx.x;
    const int n0 = blockIdx.y * 128;
    const int b  = blockIdx.z;
    const int t = threadIdx.x, warp = t >> 5, lane = t & 31;
    const int g4 = lane >> 2, l4 = lane & 3;
    const int warpM = (warp >> 2) * 32, warpN = (warp & 3) * 32;

    __shared__ __half As[2][64][40];
    __shared__ __half Bs[2][128][40];
    const uint32_t sAs = (uint32_t)__cvta_generic_to_shared(&As[0][0][0]);
    const uint32_t sBs = (uint32_t)__cvta_generic_to_shared(&Bs[0][0][0]);

    float acc[2][4][4] = {};

    const int r0 = mb * 2;
    const __half* inb = in + (size_t)b * NNODES * KDIM;

    // A-fill coords: thread t -> row am (0..63), uint4 slot aq (0..3)
    const int am = t >> 2, aq = t & 3;
    const int agr = r0 + (am >> 5), agc = am & 31;
    const __half* abp = inb + (size_t)(agr * GRID_W + agc) * KDIM + aq * 8;
    const float dC = disv(agr, agc);
    const float dU = (agr > 0)          ? disv(agr - 1, agc) : 0.f;
    const float dD = (agr < GRID_W - 1) ? disv(agr + 1, agc) : 0.f;
    const float dL = (agc > 0)          ? disv(agr, agc - 1) : 0.f;
    const float dR = (agc < GRID_W - 1) ? disv(agr, agc + 1) : 0.f;
    const uint32_t aStsOff = (uint32_t)am * 80 + aq * 16;

    // B-fill coords: 2 slots (rows bn and bn+64), cp.async 16B each
    const int bn = t >> 2, bq = t & 3;
    const __half* wp0 = W + (size_t)(n0 + bn) * KDIM + bq * 8;
    const __half* wp1 = wp0 + (size_t)64 * KDIM;
    const uint32_t bStsOff0 = (uint32_t)bn * 80 + bq * 16;
    const uint32_t bStsOff1 = bStsOff0 + 64 * 80;

    // ldmatrix addresses (stage 0, kk = 0)
    const int lmr = lane & 15, lmc = (lane >> 4) * 8;
    uint32_t aLd0 = sAs + (uint32_t)(warpM + lmr) * 80 + lmc * 2;
    uint32_t aLd1 = aLd0 + 16 * 80;
    const int bqw = lane >> 3, brw = lane & 7;
    const int bRowOff = (bqw & 2) ? 8 : 0, bColOff = (bqw & 1) ? 8 : 0;
    uint32_t bLd0 = sBs + (uint32_t)(warpN + bRowOff + brw) * 80 + bColOff * 2;
    uint32_t bLd1 = bLd0 + 16 * 80;

    const uint4 Z = make_uint4(0, 0, 0, 0);
    uint4 aC, uU, uD, uL, uR;

    // ---- prologue: chunk 0 ----
    cpa16(sBs + bStsOff0, wp0);
    cpa16(sBs + bStsOff1, wp1);
    asm volatile("cp.async.commit_group;");
    aC = *(const uint4*)abp;
    uU = dU != 0.f ? *(const uint4*)(abp - GRID_W * KDIM) : Z;
    uD = dD != 0.f ? *(const uint4*)(abp + GRID_W * KDIM) : Z;
    uL = dL != 0.f ? *(const uint4*)(abp - KDIM) : Z;
    uR = dR != 0.f ? *(const uint4*)(abp + KDIM) : Z;
    {
        float s[8] = {};
        h8fma(s, aC, dC);
        if (dU != 0.f) h8fma(s, uU, dU);
        if (dD != 0.f) h8fma(s, uD, dD);
        if (dL != 0.f) h8fma(s, uL, dL);
        if (dR != 0.f) h8fma(s, uR, dR);
        uint4 o;
        *(__half2*)&o.x = __floats2half2_rn(dC * s[0], dC * s[1]);
        *(__half2*)&o.y = __floats2half2_rn(dC * s[2], dC * s[3]);
        *(__half2*)&o.z = __floats2half2_rn(dC * s[4], dC * s[5]);
        *(__half2*)&o.w = __floats2half2_rn(dC * s[6], dC * s[7]);
        *(uint4*)&As[0][am][aq * 8] = o;
    }
    asm volatile("cp.async.wait_group 0;");
    __syncthreads();

    uint32_t st = 0;   // current stage (0/1)
    for (int c = 0; c < 8; ++c) {
        const bool more = (c < 7);
        if (more) {   // issue next-chunk loads before mma
            const int k1 = (c + 1) * 32;
            cpa16(sBs + (st ^ 1) * BS_ST + bStsOff0, wp0 + k1);
            cpa16(sBs + (st ^ 1) * BS_ST + bStsOff1, wp1 + k1);
            asm volatile("cp.async.commit_group;");
            const __half* ap = abp + k1;
            aC = *(const uint4*)ap;
            uU = dU != 0.f ? *(const uint4*)(ap - GRID_W * KDIM) : Z;
            uD = dD != 0.f ? *(const uint4*)(ap + GRID_W * KDIM) : Z;
            uL = dL != 0.f ? *(const uint4*)(ap - KDIM) : Z;
            uR = dR != 0.f ? *(const uint4*)(ap + KDIM) : Z;
        }

        // ---- mma on stage st ----
        const uint32_t aBase = st * AS_ST, bBase = st * BS_ST;
        #pragma unroll
        for (int kk = 0; kk < 32; kk += 16) {
            uint32_t af[2][4], bf[2][4];
            ldsm4(af[0], aLd0 + aBase + kk * 2);
            ldsm4(af[1], aLd1 + aBase + kk * 2);
            ldsm4(bf[0], bLd0 + bBase + kk * 2);
            ldsm4(bf[1], bLd1 + bBase + kk * 2);
            #pragma unroll
            for (int mi = 0; mi < 2; mi++)
                #pragma unroll
                for (int ni = 0; ni < 4; ni++) {
                    uint32_t b0 = bf[ni >> 1][(ni & 1) * 2];
                    uint32_t b1 = bf[ni >> 1][(ni & 1) * 2 + 1];
                    asm volatile(
                        "mma.sync.aligned.m16n8k16.row.col.f32.f16.f16.f32 "
                        "{%0,%1,%2,%3},{%4,%5,%6,%7},{%8,%9},{%0,%1,%2,%3};\n"
                        : "+f"(acc[mi][ni][0]), "+f"(acc[mi][ni][1]),
                          "+f"(acc[mi][ni][2]), "+f"(acc[mi][ni][3])
                        : "r"(af[mi][0]), "r"(af[mi][1]),
                          "r"(af[mi][2]), "r"(af[mi][3]),
                          "r"(b0), "r"(b1));
                }
        }

        if (more) {   // stencil -> As[st^1], then flip
            float s[8] = {};
            h8fma(s, aC, dC);
            if (dU != 0.f) h8fma(s, uU, dU);
            if (dD != 0.f) h8fma(s, uD, dD);
            if (dL != 0.f) h8fma(s, uL, dL);
            if (dR != 0.f) h8fma(s, uR, dR);
            uint4 o;
            *(__half2*)&o.x = __floats2half2_rn(dC * s[0], dC * s[1]);
            *(__half2*)&o.y = __floats2half2_rn(dC * s[2], dC * s[3]);
            *(__half2*)&o.z = __floats2half2_rn(dC * s[4], dC * s[5]);
            *(__half2*)&o.w = __floats2half2_rn(dC * s[6], dC * s[7]);
            *(uint4*)&As[st ^ 1][am][aq * 8] = o;
            asm volatile("cp.async.wait_group 0;");
            __syncthreads();
            st ^= 1;
        }
    }

    // ---- epilogue: + rowsum*bias, ReLU, fp16 store ----
    #pragma unroll
    for (int mi = 0; mi < 2; mi++) {
        #pragma unroll
        for (int r = 0; r < 2; r++) {
            int m = warpM + mi * 16 + g4 + 8 * r;
            int gr = r0 + (m >> 5), gc = m & 31;
            float rs = rowsumv(gr, gc);
            __half* op = out + ((size_t)b * NNODES + gr * GRID_W + gc) * HOUT + n0;
            #pragma unroll
            for (int ni = 0; ni < 4; ni++) {
                int n = warpN + ni * 8 + 2 * l4;
                float vx = fmaxf(fmaf(rs, bias[n0 + n    ], acc[mi][ni][2 * r    ]), 0.f);
                float vy = fmaxf(fmaf(rs, bias[n0 + n + 1], acc[mi][ni][2 * r + 1]), 0.f);
                *(__half2*)(op + n) = __floats2half2_rn(vx, vy);
            }
        }
    }
}

// ---------------------------------------------------------------------------
// Classifier: out[b][c] = sum_i h3[b][i]*Wc[c][i].  uint2 (4-half) loads,
// 4 batches x 10 classes per CTA, K split 16 ways.
// ---------------------------------------------------------------------------
__global__ void cls_partial_kernel(const uint2* __restrict__ h,
                                   const uint2* __restrict__ Wc,
                                   float* __restrict__ part) {
    const int ks = blockIdx.x;   // 0..15
    const int bg = blockIdx.y;   // 0..63 (groups of 4 batches)
    const int t  = threadIdx.x;  // 256
    float acc[10][4] = {};
    const int base = ks * 2048;  // uint2 units (K=32768 uint2 total)
    const uint2* hb = h + (size_t)(bg * 4) * 32768;

    #pragma unroll
    for (int it = 0; it < 8; ++it) {
        int idx = base + it * 256 + t;
        float2 wf[10][2];
        #pragma unroll
        for (int c = 0; c < 10; c++) {
            uint2 w = Wc[(size_t)c * 32768 + idx];
            wf[c][0] = __half22float2(*(__half2*)&w.x);
            wf[c][1] = __half22float2(*(__half2*)&w.y);
        }
        #pragma unroll
        for (int g = 0; g < 4; g++) {
            uint2 hv = hb[(size_t)g * 32768 + idx];
            float2 h0 = __half22float2(*(__half2*)&hv.x);
            float2 h1 = __half22float2(*(__half2*)&hv.y);
            #pragma unroll
            for (int c = 0; c < 10; c++)
                acc[c][g] = fmaf(h0.x, wf[c][0].x, fmaf(h0.y, wf[c][0].y,
                            fmaf(h1.x, wf[c][1].x, fmaf(h1.y, wf[c][1].y,
                                 acc[c][g]))));
        }
    }
    #pragma unroll
    for (int c = 0; c < 10; c++)
        #pragma unroll
        for (int g = 0; g < 4; g++) {
            float v = acc[c][g];
            for (int o = 16; o; o >>= 1) v += __shfl_down_sync(0xffffffffu, v, o);
            acc[c][g] = v;
        }
    __shared__ float red[8][40];
    if ((t & 31) == 0) {
        int w = t >> 5;
        #pragma unroll
        for (int c = 0; c < 10; c++)
            #pragma unroll
            for (int g = 0; g < 4; g++) red[w][c * 4 + g] = acc[c][g];
    }
    __syncthreads();
    if (t < 40) {
        float s = 0.f;
        #pragma unroll
        for (int w = 0; w < 8; w++) s += red[w][t];
        part[ks * 2560 + bg * 40 + t] = s;
    }
}

__global__ void cls_final_kernel(const float* __restrict__ part,
                                 const float* __restrict__ bc,
                                 float* __restrict__ out) {
    int i = blockIdx.x * 256 + threadIdx.x;
    if (i >= 2560) return;
    int b = i / 10, c = i % 10;
    int bg = b >> 2, g = b & 3;
    float s = bc[c];
    #pragma unroll
    for (int ks = 0; ks < 16; ks++)
        s += part[ks * 2560 + bg * 40 + c * 4 + g];
    out[i] = s;
}

// ---------------------------------------------------------------------------
extern "C" void kernel_launch(void* const* d_in, const int* in_sizes, int n_in,
                              void* d_out, int out_size) {
    const float* x  = (const float*)d_in[0];
    const float* W1 = (const float*)d_in[1];
    const float* b1 = (const float*)d_in[2];
    const float* W2 = (const float*)d_in[3];
    const float* b2 = (const float*)d_in[4];
    const float* W3 = (const float*)d_in[5];
    const float* b3 = (const float*)d_in[6];
    const float* Wc = (const float*)d_in[7];
    const float* bc = (const float*)d_in[8];
    float* out = (float*)d_out;

    __half *h1, *h2, *w;
    float *part;
    cudaGetSymbolAddress((void**)&h1, g_h1);
    cudaGetSymbolAddress((void**)&h2, g_h2);
    cudaGetSymbolAddress((void**)&w,  g_w);
    cudaGetSymbolAddress((void**)&part, g_part);

    convert_w_kernel<<<5120, 256>>>(W2, W3, Wc, w);
    layer1_kernel<<<dim3(GRID_W, BATCH), 256>>>(x, W1, b1, h1);
    gcn_gemm_v3<<<dim3(16, 2, BATCH), 256>>>(h1, w, b2, h2, 256);
    gcn_gemm_v3<<<dim3(16, 1, BATCH), 256>>>(h2, w + 65536, b3, h1, 128);
    cls_partial_kernel<<<dim3(16, 64), 256>>>((const uint2*)h1,
                                              (const uint2*)(w + 98304), part);
    cls_final_kernel<<<10, 256>>>(part, bc, out);
}

// round 6
// speedup vs baseline: 2.2378x; 1.1913x over previous
#include <cuda_runtime.h>
#include <cuda_fp16.h>
#include <cstdint>

#define GRID_W 32
#define NNODES 1024
#define BATCH 256
#define KDIM 256

// Scratch (device globals: no allocations allowed)
__device__ __half g_b1[BATCH * NNODES * 256];          // agg1, later agg2
__device__ __half g_b2[BATCH * NNODES * 256];          // h2, later h3
__device__ __half g_w[65536 + 32768 + 1310720];        // fp16 W2|W3|Wc
__device__ float  g_part[16 * 2560];

// ---------------------------------------------------------------------------
// Stencil weights: adj = D^-1/2 (A+I) D^-1/2, deg in {3,4,5}
// ---------------------------------------------------------------------------
__device__ __forceinline__ float disv(int i, int j) {
    int deg = 1 + (i > 0) + (i < GRID_W - 1) + (j > 0) + (j < GRID_W - 1);
    return deg == 5 ? 0.4472135954999579f
         : (deg == 4 ? 0.5f : 0.5773502691896258f);
}
__device__ __forceinline__ float rowsumv(int i, int j) {
    float d = disv(i, j);
    float s = d;
    if (i > 0)          s += disv(i - 1, j);
    if (i < GRID_W - 1) s += disv(i + 1, j);
    if (j > 0)          s += disv(i, j - 1);
    if (j < GRID_W - 1) s += disv(i, j + 1);
    return d * s;
}
__device__ __forceinline__ void h8fma(float s[8], uint4 u, float w) {
    __half2 h0 = *(__half2*)&u.x, h1 = *(__half2*)&u.y;
    __half2 h2 = *(__half2*)&u.z, h3 = *(__half2*)&u.w;
    float2 f;
    f = __half22float2(h0); s[0] = fmaf(w, f.x, s[0]); s[1] = fmaf(w, f.y, s[1]);
    f = __half22float2(h1); s[2] = fmaf(w, f.x, s[2]); s[3] = fmaf(w, f.y, s[3]);
    f = __half22float2(h2); s[4] = fmaf(w, f.x, s[4]); s[5] = fmaf(w, f.y, s[5]);
    f = __half22float2(h3); s[6] = fmaf(w, f.x, s[6]); s[7] = fmaf(w, f.y, s[7]);
}
__device__ __forceinline__ void ldsm4(uint32_t r[4], uint32_t addr) {
    asm volatile("ldmatrix.sync.aligned.m8n8.x4.shared.b16 {%0,%1,%2,%3}, [%4];"
                 : "=r"(r[0]), "=r"(r[1]), "=r"(r[2]), "=r"(r[3]) : "r"(addr));
}
__device__ __forceinline__ void cpa16(uint32_t dst, const void* src) {
    asm volatile("cp.async.ca.shared.global [%0], [%1], 16;" :: "r"(dst), "l"(src));
}

// ---------------------------------------------------------------------------
// Pre-convert weights fp32 -> fp16 (W2 | W3 | Wc packed)
// ---------------------------------------------------------------------------
__global__ void convert_w_kernel(const float* __restrict__ W2,
                                 const float* __restrict__ W3,
                                 const float* __restrict__ Wc,
                                 __half* __restrict__ o) {
    int i = blockIdx.x * 256 + threadIdx.x;
    if (i < 65536)   o[i] = __float2half(W2[i]);
    if (i < 32768)   o[65536 + i] = __float2half(W3[i]);
    if (i < 1310720) o[98304 + i] = __float2half(Wc[i]);
}

// ---------------------------------------------------------------------------
// Layer 1 fused through aggregation: writes agg1 = adj @ relu(adj@(gW1)+rs*b1)
// directly (h1 recomputed for neighbor rows; sliding window along gc).
// CTA = (grid row, batch), 256 threads = output feature.
// ---------------------------------------------------------------------------
__global__ void layer1_kernel(const float* __restrict__ x,
                              const float* __restrict__ W1,
                              const float* __restrict__ b1,
                              __half* __restrict__ out) {
    const int gr = blockIdx.x, b = blockIdx.y, t = threadIdx.x;
    __shared__ float aggg[3][32][3];   // adj@g for rows gr-1..gr+1
    __shared__ float rs_s[3][32];      // rowsum for those rows

    if (t < 96) {
        const int f = t >> 5, gc = t & 31;
        #pragma unroll
        for (int r = 0; r < 3; ++r) {
            int row = gr - 1 + r;
            float v = 0.f;
            if (row >= 0 && row < GRID_W) {
                const float* xp = x + ((size_t)(b * 3 + f)) * NNODES;
                float dm = disv(row, gc);
                float a = dm * xp[row * 32 + gc];
                if (row > 0)  a = fmaf(disv(row - 1, gc), xp[(row - 1) * 32 + gc], a);
                if (row < 31) a = fmaf(disv(row + 1, gc), xp[(row + 1) * 32 + gc], a);
                if (gc > 0)   a = fmaf(disv(row, gc - 1), xp[row * 32 + gc - 1], a);
                if (gc < 31)  a = fmaf(disv(row, gc + 1), xp[row * 32 + gc + 1], a);
                v = dm * a;
            }
            aggg[r][gc][f] = v;
            if (f == 0) rs_s[r][gc] = (row >= 0 && row < GRID_W) ? rowsumv(row, gc) : 0.f;
        }
    }
    __syncthreads();

    const float w0 = W1[t * 3 + 0], w1 = W1[t * 3 + 1], w2 = W1[t * 3 + 2];
    const float bb = b1[t];
    __half* op = out + ((size_t)b * NNODES + gr * 32) * 256 + t;

    // hval(r, gc) = relu(aggg.w + rs*bb)
    auto hval = [&](int r, int gc) {
        float v = fmaf(aggg[r][gc][0], w0,
                  fmaf(aggg[r][gc][1], w1,
                  fmaf(aggg[r][gc][2], w2, rs_s[r][gc] * bb)));
        return fmaxf(v, 0.f);
    };

    float hc_prev = 0.f, hc_cur = hval(1, 0), hc_next;
    #pragma unroll 4
    for (int gc = 0; gc < 32; ++gc) {
        hc_next = (gc < 31) ? hval(1, gc + 1) : 0.f;
        float s = disv(gr, gc) * hc_cur;
        if (gr > 0)  s = fmaf(disv(gr - 1, gc), hval(0, gc), s);
        if (gr < 31) s = fmaf(disv(gr + 1, gc), hval(2, gc), s);
        if (gc > 0)  s = fmaf(disv(gr, gc - 1), hc_prev, s);
        if (gc < 31) s = fmaf(disv(gr, gc + 1), hc_next, s);
        op[(size_t)gc * 256] = __float2half(disv(gr, gc) * s);
        hc_prev = hc_cur; hc_cur = hc_next;
    }
}

// ---------------------------------------------------------------------------
// Standalone aggregation: o[b][m][f] = sum_n adj[m][n] h[b][n][f]  (fp16, F=256)
// CTA = (grid row, batch), 256 threads, 4 uint4 (8 halfs) each.
// ---------------------------------------------------------------------------
__global__ void agg_kernel(const __half* __restrict__ h, __half* __restrict__ o) {
    const int gr = blockIdx.x, b = blockIdx.y, t = threadIdx.x;
    const __half* hb = h + (size_t)b * NNODES * 256;
    __half* ob = o + (size_t)b * NNODES * 256;
    #pragma unroll
    for (int i = 0; i < 4; ++i) {
        int u = i * 256 + t;
        int gc = u >> 5, q = u & 31;
        const __half* p = hb + (size_t)(gr * 32 + gc) * 256 + q * 8;
        float dC = disv(gr, gc);
        float s[8] = {};
        h8fma(s, *(const uint4*)p, dC);
        if (gr > 0)  h8fma(s, *(const uint4*)(p - 32 * 256), disv(gr - 1, gc));
        if (gr < 31) h8fma(s, *(const uint4*)(p + 32 * 256), disv(gr + 1, gc));
        if (gc > 0)  h8fma(s, *(const uint4*)(p - 256), disv(gr, gc - 1));
        if (gc < 31) h8fma(s, *(const uint4*)(p + 256), disv(gr, gc + 1));
        uint4 v;
        *(__half2*)&v.x = __floats2half2_rn(dC * s[0], dC * s[1]);
        *(__half2*)&v.y = __floats2half2_rn(dC * s[2], dC * s[3]);
        *(__half2*)&v.z = __floats2half2_rn(dC * s[4], dC * s[5]);
        *(__half2*)&v.w = __floats2half2_rn(dC * s[6], dC * s[7]);
        *(uint4*)(ob + (size_t)(gr * 32 + gc) * 256 + q * 8) = v;
    }
}

// ---------------------------------------------------------------------------
// Pure dense GEMM + bias*rowsum + ReLU (fp16 mma, cp.async both operands,
// double-buffered).  out[b][m][n] = relu(A[b][m][:]·W[n][:] + rowsum(m)*bias[n])
// CTA: 256 thr, M=128 x N=128, K chunks of 32; 8 warps at 64x32.
// grid = (HOUT/128, 8, batch)  -- x fastest so N-blocks share A in L2.
// ---------------------------------------------------------------------------
#define STG 10240   // bytes per stage per operand (128 rows * 80B)

__global__ __launch_bounds__(256, 2)
void gemm_f16(const __half* __restrict__ A,
              const __half* __restrict__ W,
              const float* __restrict__ bias,
              __half* __restrict__ out, int HOUT) {
    const int n0 = blockIdx.x * 128;
    const int mb = blockIdx.y;
    const int b  = blockIdx.z;
    const int t = threadIdx.x, warp = t >> 5, lane = t & 31;
    const int g4 = lane >> 2, l4 = lane & 3;
    const int warpM = (warp >> 2) * 64, warpN = (warp & 3) * 32;

    __shared__ __half As[2][128][40];
    __shared__ __half Bs[2][128][40];
    const uint32_t sA = (uint32_t)__cvta_generic_to_shared(&As[0][0][0]);
    const uint32_t sB = (uint32_t)__cvta_generic_to_shared(&Bs[0][0][0]);

    float acc[4][4][4] = {};

    const __half* Ab = A + ((size_t)b * NNODES + mb * 128) * KDIM;
    const __half* Wb = W + (size_t)n0 * KDIM;

    // fill: 2 slots per thread per operand (rows t>>2 and 64+(t>>2))
    const int fr = t >> 2, fq = t & 3;
    const uint32_t fOff0 = (uint32_t)fr * 80 + fq * 16;
    const uint32_t fOff1 = fOff0 + 64 * 80;
    const __half* aSrc0 = Ab + (size_t)fr * KDIM + fq * 8;
    const __half* aSrc1 = aSrc0 + (size_t)64 * KDIM;
    const __half* bSrc0 = Wb + (size_t)fr * KDIM + fq * 8;
    const __half* bSrc1 = bSrc0 + (size_t)64 * KDIM;

    auto fill = [&](int c, int st) {
        const uint32_t da = sA + st * STG, db = sB + st * STG;
        const int k = c * 32;
        cpa16(da + fOff0, aSrc0 + k);
        cpa16(da + fOff1, aSrc1 + k);
        cpa16(db + fOff0, bSrc0 + k);
        cpa16(db + fOff1, bSrc1 + k);
        asm volatile("cp.async.commit_group;");
    };

    // ldmatrix base addresses
    const int lmr = lane & 15, lmc = (lane >> 4) * 8;
    uint32_t aLd[4];
    #pragma unroll
    for (int mi = 0; mi < 4; ++mi)
        aLd[mi] = sA + (uint32_t)(warpM + mi * 16 + lmr) * 80 + lmc * 2;
    const int bqw = lane >> 3, brw = lane & 7;
    const int bRowOff = (bqw & 2) ? 8 : 0, bColOff = (bqw & 1) ? 8 : 0;
    uint32_t bLd[2];
    #pragma unroll
    for (int nj = 0; nj < 2; ++nj)
        bLd[nj] = sB + (uint32_t)(warpN + nj * 16 + bRowOff + brw) * 80 + bColOff * 2;

    fill(0, 0);

    for (int c = 0; c < 8; ++c) {
        const int st = c & 1;
        if (c < 7) {
            fill(c + 1, st ^ 1);
            asm volatile("cp.async.wait_group 1;");
        } else {
            asm volatile("cp.async.wait_group 0;");
        }
        __syncthreads();

        const uint32_t so = st * STG;
        #pragma unroll
        for (int kk = 0; kk < 32; kk += 16) {
            uint32_t af[4][4], bf[2][4];
            #pragma unroll
            for (int mi = 0; mi < 4; ++mi) ldsm4(af[mi], aLd[mi] + so + kk * 2);
            #pragma unroll
            for (int nj = 0; nj < 2; ++nj) ldsm4(bf[nj], bLd[nj] + so + kk * 2);
            #pragma unroll
            for (int mi = 0; mi < 4; ++mi)
                #pragma unroll
                for (int ni = 0; ni < 4; ++ni) {
                    uint32_t b0 = bf[ni >> 1][(ni & 1) * 2];
                    uint32_t b1 = bf[ni >> 1][(ni & 1) * 2 + 1];
                    asm volatile(
                        "mma.sync.aligned.m16n8k16.row.col.f32.f16.f16.f32 "
                        "{%0,%1,%2,%3},{%4,%5,%6,%7},{%8,%9},{%0,%1,%2,%3};\n"
                        : "+f"(acc[mi][ni][0]), "+f"(acc[mi][ni][1]),
                          "+f"(acc[mi][ni][2]), "+f"(acc[mi][ni][3])
                        : "r"(af[mi][0]), "r"(af[mi][1]),
                          "r"(af[mi][2]), "r"(af[mi][3]),
                          "r"(b0), "r"(b1));
                }
        }
        __syncthreads();
    }

    // epilogue: + rowsum*bias, ReLU, fp16 store
    #pragma unroll
    for (int mi = 0; mi < 4; ++mi) {
        #pragma unroll
        for (int r = 0; r < 2; ++r) {
            int m = warpM + mi * 16 + g4 + 8 * r;
            int node = mb * 128 + m;
            int gr = node >> 5, gc = node & 31;
            float rs = rowsumv(gr, gc);
            __half* op = out + ((size_t)b * NNODES + node) * HOUT + n0;
            #pragma unroll
            for (int ni = 0; ni < 4; ++ni) {
                int n = warpN + ni * 8 + 2 * l4;
                float vx = fmaxf(fmaf(rs, bias[n0 + n    ], acc[mi][ni][2 * r    ]), 0.f);
                float vy = fmaxf(fmaf(rs, bias[n0 + n + 1], acc[mi][ni][2 * r + 1]), 0.f);
                *(__half2*)(op + n) = __floats2half2_rn(vx, vy);
            }
        }
    }
}

// ---------------------------------------------------------------------------
// Classifier: out[b][c] = sum_i h3[b][i]*Wc[c][i].  fp16 uint2 loads,
// 4 batches x 10 classes per CTA, K split 16 ways.
// ---------------------------------------------------------------------------
__global__ void cls_partial_kernel(const uint2* __restrict__ h,
                                   const uint2* __restrict__ Wc,
                                   float* __restrict__ part) {
    const int ks = blockIdx.x, bg = blockIdx.y, t = threadIdx.x;
    float acc[10][4] = {};
    const int base = ks * 2048;
    const uint2* hb = h + (size_t)(bg * 4) * 32768;

    #pragma unroll
    for (int it = 0; it < 8; ++it) {
        int idx = base + it * 256 + t;
        float2 wf[10][2];
        #pragma unroll
        for (int c = 0; c < 10; c++) {
            uint2 w = Wc[(size_t)c * 32768 + idx];
            wf[c][0] = __half22float2(*(__half2*)&w.x);
            wf[c][1] = __half22float2(*(__half2*)&w.y);
        }
        #pragma unroll
        for (int g = 0; g < 4; g++) {
            uint2 hv = hb[(size_t)g * 32768 + idx];
            float2 h0 = __half22float2(*(__half2*)&hv.x);
            float2 h1 = __half22float2(*(__half2*)&hv.y);
            #pragma unroll
            for (int c = 0; c < 10; c++)
                acc[c][g] = fmaf(h0.x, wf[c][0].x, fmaf(h0.y, wf[c][0].y,
                            fmaf(h1.x, wf[c][1].x, fmaf(h1.y, wf[c][1].y,
                                 acc[c][g]))));
        }
    }
    #pragma unroll
    for (int c = 0; c < 10; c++)
        #pragma unroll
        for (int g = 0; g < 4; g++) {
            float v = acc[c][g];
            for (int o = 16; o; o >>= 1) v += __shfl_down_sync(0xffffffffu, v, o);
            acc[c][g] = v;
        }
    __shared__ float red[8][40];
    if ((t & 31) == 0) {
        int w = t >> 5;
        #pragma unroll
        for (int c = 0; c < 10; c++)
            #pragma unroll
            for (int g = 0; g < 4; g++) red[w][c * 4 + g] = acc[c][g];
    }
    __syncthreads();
    if (t < 40) {
        float s = 0.f;
        #pragma unroll
        for (int w = 0; w < 8; w++) s += red[w][t];
        part[ks * 2560 + bg * 40 + t] = s;
    }
}

__global__ void cls_final_kernel(const float* __restrict__ part,
                                 const float* __restrict__ bc,
                                 float* __restrict__ out) {
    int i = blockIdx.x * 256 + threadIdx.x;
    if (i >= 2560) return;
    int b = i / 10, c = i % 10;
    int bg = b >> 2, g = b & 3;
    float s = bc[c];
    #pragma unroll
    for (int ks = 0; ks < 16; ks++)
        s += part[ks * 2560 + bg * 40 + c * 4 + g];
    out[i] = s;
}

// ---------------------------------------------------------------------------
extern "C" void kernel_launch(void* const* d_in, const int* in_sizes, int n_in,
                              void* d_out, int out_size) {
    const float* x  = (const float*)d_in[0];
    const float* W1 = (const float*)d_in[1];
    const float* b1 = (const float*)d_in[2];
    const float* W2 = (const float*)d_in[3];
    const float* b2 = (const float*)d_in[4];
    const float* W3 = (const float*)d_in[5];
    const float* b3 = (const float*)d_in[6];
    const float* Wc = (const float*)d_in[7];
    const float* bc = (const float*)d_in[8];
    float* out = (float*)d_out;

    __half *buf1, *buf2, *w;
    float *part;
    cudaGetSymbolAddress((void**)&buf1, g_b1);
    cudaGetSymbolAddress((void**)&buf2, g_b2);
    cudaGetSymbolAddress((void**)&w,   g_w);
    cudaGetSymbolAddress((void**)&part, g_part);

    convert_w_kernel<<<5120, 256>>>(W2, W3, Wc, w);
    // layer1 (fused through aggregation): x -> agg1 (buf1)
    layer1_kernel<<<dim3(GRID_W, BATCH), 256>>>(x, W1, b1, buf1);
    // layer2: h2 = relu(agg1 @ W2^T + rs*b2) -> buf2
    gemm_f16<<<dim3(2, 8, BATCH), 256>>>(buf1, w, b2, buf2, 256);
    // aggregate h2 -> agg2 (buf1)
    agg_kernel<<<dim3(GRID_W, BATCH), 256>>>(buf2, buf1);
    // layer3: h3 = relu(agg2 @ W3^T + rs*b3) -> buf2
    gemm_f16<<<dim3(1, 8, BATCH), 256>>>(buf1, w + 65536, b3, buf2, 128);
    // classifier
    cls_partial_kernel<<<dim3(16, 64), 256>>>((const uint2*)buf2,
                                              (const uint2*)(w + 98304), part);
    cls_final_kernel<<<10, 256>>>(part, bc, out);
}

// round 7
// speedup vs baseline: 2.2967x; 1.0263x over previous
#include <cuda_runtime.h>
#include <cuda_fp16.h>
#include <cstdint>

#define GRID_W 32
#define NNODES 1024
#define BATCH 256
#define KDIM 256

// Scratch (device globals: no allocations allowed)
__device__ __half g_b1[BATCH * NNODES * 256];          // agg1, later h3
__device__ __half g_b2[BATCH * NNODES * 256];          // t3
__device__ __half g_w[65536 + 32768 + 1310720];        // fp16 W2|W3|Wc
__device__ float  g_part[16 * 2560];

// ---------------------------------------------------------------------------
// Stencil weights: adj = D^-1/2 (A+I) D^-1/2, deg in {3,4,5}
// ---------------------------------------------------------------------------
__device__ __forceinline__ float disv(int i, int j) {
    int deg = 1 + (i > 0) + (i < GRID_W - 1) + (j > 0) + (j < GRID_W - 1);
    return deg == 5 ? 0.4472135954999579f
         : (deg == 4 ? 0.5f : 0.5773502691896258f);
}
__device__ __forceinline__ float rowsumv(int i, int j) {
    float d = disv(i, j);
    float s = d;
    if (i > 0)          s += disv(i - 1, j);
    if (i < GRID_W - 1) s += disv(i + 1, j);
    if (j > 0)          s += disv(i, j - 1);
    if (j < GRID_W - 1) s += disv(i, j + 1);
    return d * s;
}
__device__ __forceinline__ void h8fma(float s[8], uint4 u, float w) {
    __half2 h0 = *(__half2*)&u.x, h1 = *(__half2*)&u.y;
    __half2 h2 = *(__half2*)&u.z, h3 = *(__half2*)&u.w;
    float2 f;
    f = __half22float2(h0); s[0] = fmaf(w, f.x, s[0]); s[1] = fmaf(w, f.y, s[1]);
    f = __half22float2(h1); s[2] = fmaf(w, f.x, s[2]); s[3] = fmaf(w, f.y, s[3]);
    f = __half22float2(h2); s[4] = fmaf(w, f.x, s[4]); s[5] = fmaf(w, f.y, s[5]);
    f = __half22float2(h3); s[6] = fmaf(w, f.x, s[6]); s[7] = fmaf(w, f.y, s[7]);
}
__device__ __forceinline__ void ldsm4(uint32_t r[4], uint32_t addr) {
    asm volatile("ldmatrix.sync.aligned.m8n8.x4.shared.b16 {%0,%1,%2,%3}, [%4];"
                 : "=r"(r[0]), "=r"(r[1]), "=r"(r[2]), "=r"(r[3]) : "r"(addr));
}
__device__ __forceinline__ void cpa16(uint32_t dst, const void* src) {
    asm volatile("cp.async.ca.shared.global [%0], [%1], 16;" :: "r"(dst), "l"(src));
}

// ---------------------------------------------------------------------------
// Pre-convert weights fp32 -> fp16 (W2 | W3 | Wc packed)
// ---------------------------------------------------------------------------
__global__ void convert_w_kernel(const float* __restrict__ W2,
                                 const float* __restrict__ W3,
                                 const float* __restrict__ Wc,
                                 __half* __restrict__ o) {
    int i = blockIdx.x * 256 + threadIdx.x;
    if (i < 65536)   o[i] = __float2half(W2[i]);
    if (i < 32768)   o[65536 + i] = __float2half(W3[i]);
    if (i < 1310720) o[98304 + i] = __float2half(Wc[i]);
}

// ---------------------------------------------------------------------------
// Layer 1 fused through aggregation: agg1 = adj @ relu(adj@(x~W1)+rs*b1)
// (h1 recomputed for neighbor rows; sliding window along gc)
// ---------------------------------------------------------------------------
__global__ void layer1_kernel(const float* __restrict__ x,
                              const float* __restrict__ W1,
                              const float* __restrict__ b1,
                              __half* __restrict__ out) {
    const int gr = blockIdx.x, b = blockIdx.y, t = threadIdx.x;
    __shared__ float aggg[3][32][3];
    __shared__ float rs_s[3][32];

    if (t < 96) {
        const int f = t >> 5, gc = t & 31;
        #pragma unroll
        for (int r = 0; r < 3; ++r) {
            int row = gr - 1 + r;
            float v = 0.f;
            if (row >= 0 && row < GRID_W) {
                const float* xp = x + ((size_t)(b * 3 + f)) * NNODES;
                float dm = disv(row, gc);
                float a = dm * xp[row * 32 + gc];
                if (row > 0)  a = fmaf(disv(row - 1, gc), xp[(row - 1) * 32 + gc], a);
                if (row < 31) a = fmaf(disv(row + 1, gc), xp[(row + 1) * 32 + gc], a);
                if (gc > 0)   a = fmaf(disv(row, gc - 1), xp[row * 32 + gc - 1], a);
                if (gc < 31)  a = fmaf(disv(row, gc + 1), xp[row * 32 + gc + 1], a);
                v = dm * a;
            }
            aggg[r][gc][f] = v;
            if (f == 0) rs_s[r][gc] = (row >= 0 && row < GRID_W) ? rowsumv(row, gc) : 0.f;
        }
    }
    __syncthreads();

    const float w0 = W1[t * 3 + 0], w1 = W1[t * 3 + 1], w2 = W1[t * 3 + 2];
    const float bb = b1[t];
    __half* op = out + ((size_t)b * NNODES + gr * 32) * 256 + t;

    auto hval = [&](int r, int gc) {
        float v = fmaf(aggg[r][gc][0], w0,
                  fmaf(aggg[r][gc][1], w1,
                  fmaf(aggg[r][gc][2], w2, rs_s[r][gc] * bb)));
        return fmaxf(v, 0.f);
    };

    float hc_prev = 0.f, hc_cur = hval(1, 0), hc_next;
    #pragma unroll 4
    for (int gc = 0; gc < 32; ++gc) {
        hc_next = (gc < 31) ? hval(1, gc + 1) : 0.f;
        float s = disv(gr, gc) * hc_cur;
        if (gr > 0)  s = fmaf(disv(gr - 1, gc), hval(0, gc), s);
        if (gr < 31) s = fmaf(disv(gr + 1, gc), hval(2, gc), s);
        if (gc > 0)  s = fmaf(disv(gr, gc - 1), hc_prev, s);
        if (gc < 31) s = fmaf(disv(gr, gc + 1), hc_next, s);
        op[(size_t)gc * 256] = __float2half(disv(gr, gc) * s);
        hc_prev = hc_cur; hc_cur = hc_next;
    }
}

// ---------------------------------------------------------------------------
// Fused layers 2+3:  t3 = (relu(agg1@W2^T + rs*b2)) @ W3^T
// CTA = 128 nodes x one batch.  A tile (128x256 fp16, XOR-swizzled, 64KB)
// resident in smem; phase 1 produces h2 (128x256) INTO SMEM in two N=128
// passes; phase 2 reads h2 via ldmatrix and emits t3 (128x128) to gmem.
// Weights stream as k32 chunks (pitch-40), double-buffered cp.async.
// 256 threads, 8 warps at 64x32.
// ---------------------------------------------------------------------------
#define OFF_BIAS 0
#define OFF_A    1024
#define OFF_H    (1024 + 65536)
#define OFF_W    (1024 + 2 * 65536)
#define WSTG     10240
#define SMEM23   (OFF_W + 2 * WSTG)

__global__ __launch_bounds__(256, 1)
void gemm23_kernel(const __half* __restrict__ A,
                   const __half* __restrict__ W2h,
                   const __half* __restrict__ W3h,
                   const float* __restrict__ b2,
                   __half* __restrict__ out) {
    extern __shared__ char smem[];
    const int mb = blockIdx.x, b = blockIdx.y;
    const int t = threadIdx.x, warp = t >> 5, lane = t & 31;
    const int g4 = lane >> 2, l4 = lane & 3;
    const int warpM = (warp >> 2) * 64, warpN = (warp & 3) * 32;
    const uint32_t sb = (uint32_t)__cvta_generic_to_shared(smem);
    float* biasS = (float*)(smem + OFF_BIAS);

    biasS[t] = b2[t];

    // ---- A tile -> smem (XOR-swizzled rows of 512B), via cp.async ----
    const __half* Ab = A + ((size_t)b * NNODES + mb * 128) * KDIM;
    #pragma unroll
    for (int i = 0; i < 16; ++i) {
        int u = i * 256 + t, row = u >> 5, blk = u & 31;
        cpa16(sb + OFF_A + row * 512 + (((blk ^ (row & 7)) << 4)),
              Ab + (size_t)row * 256 + blk * 8);
    }
    asm volatile("cp.async.commit_group;");

    // ---- W chunk fill: 128 rows x 32 halfs, pitch 40 ----
    auto fillW = [&](const __half* Wsrc, int c, int st) {
        #pragma unroll
        for (int i = 0; i < 2; ++i) {
            int u = i * 256 + t, row = u >> 2, blk = u & 3;
            cpa16(sb + OFF_W + st * WSTG + row * 80 + blk * 16,
                  Wsrc + (size_t)row * 256 + c * 32 + blk * 8);
        }
        asm volatile("cp.async.commit_group;");
    };

    // ---- ldmatrix address precompute ----
    uint32_t aBase[4]; int aX[4];
    #pragma unroll
    for (int mi = 0; mi < 4; ++mi) {
        int r = warpM + mi * 16 + (lane & 15);
        aBase[mi] = (uint32_t)r * 512;
        aX[mi] = r & 7;
    }
    const int lblk = lane >> 4;
    const int bqw = lane >> 3, brw = lane & 7;
    const int bRowOff = (bqw & 2) ? 8 : 0, bColOff = (bqw & 1) ? 8 : 0;
    uint32_t bOff[2];
    #pragma unroll
    for (int nj = 0; nj < 2; ++nj)
        bOff[nj] = (uint32_t)(warpN + nj * 16 + bRowOff + brw) * 80 + bColOff * 2;

    float acc[4][4][4];

    for (int pass = 0; pass < 3; ++pass) {
        const bool ph2 = (pass == 2);
        const __half* Wsrc = ph2 ? W3h : (W2h + (size_t)pass * 128 * 256);
        const uint32_t aOff = ph2 ? (sb + OFF_H) : (sb + OFF_A);

        #pragma unroll
        for (int mi = 0; mi < 4; ++mi)
            #pragma unroll
            for (int ni = 0; ni < 4; ++ni)
                #pragma unroll
                for (int q = 0; q < 4; ++q) acc[mi][ni][q] = 0.f;

        fillW(Wsrc, 0, 0);
        for (int c = 0; c < 8; ++c) {
            const int st = c & 1;
            if (c < 7) {
                fillW(Wsrc, c + 1, st ^ 1);
                asm volatile("cp.async.wait_group 1;");
            } else {
                asm volatile("cp.async.wait_group 0;");
            }
            __syncthreads();

            #pragma unroll
            for (int k2 = 0; k2 < 2; ++k2) {
                const int kb = c * 4 + k2 * 2 + lblk;
                uint32_t af[4][4], bf[2][4];
                #pragma unroll
                for (int mi = 0; mi < 4; ++mi)
                    ldsm4(af[mi], aOff + aBase[mi] + (((kb ^ aX[mi]) << 4)));
                #pragma unroll
                for (int nj = 0; nj < 2; ++nj)
                    ldsm4(bf[nj], sb + OFF_W + st * WSTG + bOff[nj] + k2 * 32);
                #pragma unroll
                for (int mi = 0; mi < 4; ++mi)
                    #pragma unroll
                    for (int ni = 0; ni < 4; ++ni) {
                        uint32_t b0 = bf[ni >> 1][(ni & 1) * 2];
                        uint32_t b1 = bf[ni >> 1][(ni & 1) * 2 + 1];
                        asm volatile(
                            "mma.sync.aligned.m16n8k16.row.col.f32.f16.f16.f32 "
                            "{%0,%1,%2,%3},{%4,%5,%6,%7},{%8,%9},{%0,%1,%2,%3};\n"
                            : "+f"(acc[mi][ni][0]), "+f"(acc[mi][ni][1]),
                              "+f"(acc[mi][ni][2]), "+f"(acc[mi][ni][3])
                            : "r"(af[mi][0]), "r"(af[mi][1]),
                              "r"(af[mi][2]), "r"(af[mi][3]),
                              "r"(b0), "r"(b1));
                    }
            }
            __syncthreads();
        }

        if (!ph2) {
            // h2 epilogue: relu(acc + rs*b2) -> swizzled smem (cols pass*128+n)
            #pragma unroll
            for (int mi = 0; mi < 4; ++mi)
                #pragma unroll
                for (int r = 0; r < 2; ++r) {
                    int m = warpM + mi * 16 + g4 + 8 * r;
                    int node = mb * 128 + m;
                    float rs = rowsumv(node >> 5, node & 31);
                    #pragma unroll
                    for (int ni = 0; ni < 4; ++ni) {
                        int col = pass * 128 + warpN + ni * 8 + 2 * l4;
                        float vx = fmaxf(fmaf(rs, biasS[col],     acc[mi][ni][2 * r    ]), 0.f);
                        float vy = fmaxf(fmaf(rs, biasS[col + 1], acc[mi][ni][2 * r + 1]), 0.f);
                        uint32_t off = OFF_H + m * 512 +
                                       (((col >> 3) ^ (m & 7)) << 4) + ((col * 2) & 15);
                        *(__half2*)(smem + off) = __floats2half2_rn(vx, vy);
                    }
                }
        } else {
            // t3 epilogue: plain store (bias/relu applied after aggregation)
            #pragma unroll
            for (int mi = 0; mi < 4; ++mi)
                #pragma unroll
                for (int r = 0; r < 2; ++r) {
                    int m = warpM + mi * 16 + g4 + 8 * r;
                    int node = mb * 128 + m;
                    __half* op = out + ((size_t)b * NNODES + node) * 128;
                    #pragma unroll
                    for (int ni = 0; ni < 4; ++ni) {
                        int n = warpN + ni * 8 + 2 * l4;
                        *(__half2*)(op + n) =
                            __floats2half2_rn(acc[mi][ni][2 * r], acc[mi][ni][2 * r + 1]);
                    }
                }
        }
    }
}

// ---------------------------------------------------------------------------
// h3 = relu(adj @ t3 + rs*b3), F = 128 fp16
// ---------------------------------------------------------------------------
__global__ void aggrelu_kernel(const __half* __restrict__ tin,
                               const float* __restrict__ b3,
                               __half* __restrict__ o) {
    const int gr = blockIdx.x, b = blockIdx.y, t = threadIdx.x;
    const __half* tb = tin + (size_t)b * NNODES * 128;
    __half* ob = o + (size_t)b * NNODES * 128;
    #pragma unroll
    for (int i = 0; i < 2; ++i) {
        int u = i * 256 + t, gc = u >> 4, q = u & 15;
        const __half* p = tb + (size_t)(gr * 32 + gc) * 128 + q * 8;
        float dC = disv(gr, gc);
        float s[8] = {};
        h8fma(s, *(const uint4*)p, dC);
        if (gr > 0)  h8fma(s, *(const uint4*)(p - 32 * 128), disv(gr - 1, gc));
        if (gr < 31) h8fma(s, *(const uint4*)(p + 32 * 128), disv(gr + 1, gc));
        if (gc > 0)  h8fma(s, *(const uint4*)(p - 128), disv(gr, gc - 1));
        if (gc < 31) h8fma(s, *(const uint4*)(p + 128), disv(gr, gc + 1));
        float rs = rowsumv(gr, gc);
        float4 bl0 = *(const float4*)(b3 + q * 8);
        float4 bl1 = *(const float4*)(b3 + q * 8 + 4);
        uint4 v;
        *(__half2*)&v.x = __floats2half2_rn(
            fmaxf(fmaf(rs, bl0.x, dC * s[0]), 0.f),
            fmaxf(fmaf(rs, bl0.y, dC * s[1]), 0.f));
        *(__half2*)&v.y = __floats2half2_rn(
            fmaxf(fmaf(rs, bl0.z, dC * s[2]), 0.f),
            fmaxf(fmaf(rs, bl0.w, dC * s[3]), 0.f));
        *(__half2*)&v.z = __floats2half2_rn(
            fmaxf(fmaf(rs, bl1.x, dC * s[4]), 0.f),
            fmaxf(fmaf(rs, bl1.y, dC * s[5]), 0.f));
        *(__half2*)&v.w = __floats2half2_rn(
            fmaxf(fmaf(rs, bl1.z, dC * s[6]), 0.f),
            fmaxf(fmaf(rs, bl1.w, dC * s[7]), 0.f));
        *(uint4*)(ob + (size_t)(gr * 32 + gc) * 128 + q * 8) = v;
    }
}

// ---------------------------------------------------------------------------
// Classifier: out[b][c] = sum_i h3[b][i]*Wc[c][i].  fp16 uint2 loads,
// 4 batches x 10 classes per CTA, K split 16 ways.
// ---------------------------------------------------------------------------
__global__ void cls_partial_kernel(const uint2* __restrict__ h,
                                   const uint2* __restrict__ Wc,
                                   float* __restrict__ part) {
    const int ks = blockIdx.x, bg = blockIdx.y, t = threadIdx.x;
    float acc[10][4] = {};
    const int base = ks * 2048;
    const uint2* hb = h + (size_t)(bg * 4) * 32768;

    #pragma unroll
    for (int it = 0; it < 8; ++it) {
        int idx = base + it * 256 + t;
        float2 wf[10][2];
        #pragma unroll
        for (int c = 0; c < 10; c++) {
            uint2 w = Wc[(size_t)c * 32768 + idx];
            wf[c][0] = __half22float2(*(__half2*)&w.x);
            wf[c][1] = __half22float2(*(__half2*)&w.y);
        }
        #pragma unroll
        for (int g = 0; g < 4; g++) {
            uint2 hv = hb[(size_t)g * 32768 + idx];
            float2 h0 = __half22float2(*(__half2*)&hv.x);
            float2 h1 = __half22float2(*(__half2*)&hv.y);
            #pragma unroll
            for (int c = 0; c < 10; c++)
                acc[c][g] = fmaf(h0.x, wf[c][0].x, fmaf(h0.y, wf[c][0].y,
                            fmaf(h1.x, wf[c][1].x, fmaf(h1.y, wf[c][1].y,
                                 acc[c][g]))));
        }
    }
    #pragma unroll
    for (int c = 0; c < 10; c++)
        #pragma unroll
        for (int g = 0; g < 4; g++) {
            float v = acc[c][g];
            for (int o = 16; o; o >>= 1) v += __shfl_down_sync(0xffffffffu, v, o);
            acc[c][g] = v;
        }
    __shared__ float red[8][40];
    if ((t & 31) == 0) {
        int w = t >> 5;
        #pragma unroll
        for (int c = 0; c < 10; c++)
            #pragma unroll
            for (int g = 0; g < 4; g++) red[w][c * 4 + g] = acc[c][g];
    }
    __syncthreads();
    if (t < 40) {
        float s = 0.f;
        #pragma unroll
        for (int w = 0; w < 8; w++) s += red[w][t];
        part[ks * 2560 + bg * 40 + t] = s;
    }
}

__global__ void cls_final_kernel(const float* __restrict__ part,
                                 const float* __restrict__ bc,
                                 float* __restrict__ out) {
    int i = blockIdx.x * 256 + threadIdx.x;
    if (i >= 2560) return;
    int b = i / 10, c = i % 10;
    int bg = b >> 2, g = b & 3;
    float s = bc[c];
    #pragma unroll
    for (int ks = 0; ks < 16; ks++)
        s += part[ks * 2560 + bg * 40 + c * 4 + g];
    out[i] = s;
}

// ---------------------------------------------------------------------------
extern "C" void kernel_launch(void* const* d_in, const int* in_sizes, int n_in,
                              void* d_out, int out_size) {
    const float* x  = (const float*)d_in[0];
    const float* W1 = (const float*)d_in[1];
    const float* b1 = (const float*)d_in[2];
    const float* W2 = (const float*)d_in[3];
    const float* b2 = (const float*)d_in[4];
    const float* W3 = (const float*)d_in[5];
    const float* b3 = (const float*)d_in[6];
    const float* Wc = (const float*)d_in[7];
    const float* bc = (const float*)d_in[8];
    float* out = (float*)d_out;

    __half *buf1, *buf2, *w;
    float *part;
    cudaGetSymbolAddress((void**)&buf1, g_b1);
    cudaGetSymbolAddress((void**)&buf2, g_b2);
    cudaGetSymbolAddress((void**)&w,   g_w);
    cudaGetSymbolAddress((void**)&part, g_part);

    cudaFuncSetAttribute(gemm23_kernel,
                         cudaFuncAttributeMaxDynamicSharedMemorySize, SMEM23);

    convert_w_kernel<<<5120, 256>>>(W2, W3, Wc, w);
    // layer1 (fused through aggregation): x -> agg1 (buf1)
    layer1_kernel<<<dim3(GRID_W, BATCH), 256>>>(x, W1, b1, buf1);
    // fused layers 2+3: agg1 -> t3 (buf2); h2 lives only in smem
    gemm23_kernel<<<dim3(8, BATCH), 256, SMEM23>>>(buf1, w, w + 65536, b2, buf2);
    // h3 = relu(adj@t3 + rs*b3) -> buf1
    aggrelu_kernel<<<dim3(GRID_W, BATCH), 256>>>(buf2, b3, buf1);
    // classifier
    cls_partial_kernel<<<dim3(16, 64), 256>>>((const uint2*)buf1,
                                              (const uint2*)(w + 98304), part);
    cls_final_kernel<<<10, 256>>>(part, bc, out);
}